// round 7
// baseline (speedup 1.0000x reference)
#include <cuda_runtime.h>
#include <cuda_bf16.h>
#include <math_constants.h>
#include <cstdint>

#define NC   81
#define NCP  96
#define BK   10
#define DIM  2048
#define NI   16384
#define NT   64          /* k-tiles of 32 fp32 dims */
#define BMG  128         /* gemm instances per block */

__device__ int   g_count;
__device__ int   g_nfix;
__device__ int   g_fix[NI];
__device__ float g_bias[NCP];
__device__ float g_mmean[NC * DIM];
__device__ float g_xn[NI];
// [tile][class][hi(32)|lo(32)] bf16 => 128B per class-row per tile
__device__ __align__(16) unsigned short g_mbf[NT * NCP * 64];

__device__ __forceinline__ uint32_t smem_u32(const void* p) {
    uint32_t a;
    asm("{ .reg .u64 t; cvta.to.shared.u64 t, %1; cvt.u32.u64 %0, t; }" : "=r"(a) : "l"(p));
    return a;
}

#define LDSM_X4(r0, r1, r2, r3, addr)                                         \
    asm volatile("ldmatrix.sync.aligned.m8n8.x4.shared.b16 {%0,%1,%2,%3}, [%4];" \
                 : "=r"(r0), "=r"(r1), "=r"(r2), "=r"(r3) : "r"(addr))

#define MMA16816(d, a, b0v, b1v)                                              \
    asm volatile("mma.sync.aligned.m16n8k16.row.col.f32.bf16.bf16.f32 "       \
                 "{%0,%1,%2,%3},{%4,%5,%6,%7},{%8,%9},{%0,%1,%2,%3};"         \
                 : "+f"((d)[0]), "+f"((d)[1]), "+f"((d)[2]), "+f"((d)[3])     \
                 : "r"((a)[0]), "r"((a)[1]), "r"((a)[2]), "r"((a)[3]),        \
                   "r"(b0v), "r"(b1v))

#define FMA2(d, a, b, c) asm("fma.rn.f32x2 %0, %1, %2, %3;" : "=l"(d) : "l"(a), "l"(b), "l"(c))
#define ADD2(d, a, b)    asm("add.rn.f32x2 %0, %1, %2;" : "=l"(d) : "l"(a), "l"(b))
#define UNPACK2(lo, hi, v) asm("mov.b64 {%0, %1}, %2;" : "=f"(lo), "=f"(hi) : "l"(v))

#define CPA16(dst, src) asm volatile("cp.async.cg.shared.global [%0], [%1], 16;" :: "r"(dst), "l"(src) : "memory")
#define CPCOMMIT()      asm volatile("cp.async.commit_group;" ::: "memory")
#define CPWAIT3()       asm volatile("cp.async.wait_group 3;" ::: "memory")

__device__ __forceinline__ unsigned pkbf(__nv_bfloat16 a, __nv_bfloat16 b) {
    return ((unsigned)__bfloat16_as_ushort(b) << 16) | (unsigned)__bfloat16_as_ushort(a);
}

// ---------------------------------------------------------------------------
// Kernel 1: class means -> fp32 plane + bf16 hi/lo planes + bias; zero pads.
// ---------------------------------------------------------------------------
__global__ void k_mean(const float* __restrict__ mem) {
    int c = blockIdx.x, tid = threadIdx.x;
    if (c == 0 && tid == 0) { g_count = 0; g_nfix = 0; }
    if (c >= NC) {
        for (int d = tid; d < DIM; d += 256) {
            int tt = d >> 5, j = d & 31;
            g_mbf[(tt * NCP + c) * 64 + j] = 0;
            g_mbf[(tt * NCP + c) * 64 + 32 + j] = 0;
        }
        return;
    }
    float part = 0.f;
    for (int d = tid; d < DIM; d += 256) {
        float s = 0.f;
#pragma unroll
        for (int b = 0; b < BK; b++) s += mem[(size_t)(c * BK + b) * DIM + d];
        float m = s * (1.0f / BK);
        g_mmean[c * DIM + d] = m;
        __nv_bfloat16 hi = __float2bfloat16_rn(m);
        __nv_bfloat16 lo = __float2bfloat16_rn(m - __bfloat162float(hi));
        int tt = d >> 5, j = d & 31;
        g_mbf[(tt * NCP + c) * 64 + j] = __bfloat16_as_ushort(hi);
        g_mbf[(tt * NCP + c) * 64 + 32 + j] = __bfloat16_as_ushort(lo);
        part += m * m;
    }
#pragma unroll
    for (int o = 16; o; o >>= 1) part += __shfl_xor_sync(0xffffffffu, part, o);
    __shared__ float rb[8];
    if ((tid & 31) == 0) rb[tid >> 5] = part;
    __syncthreads();
    if (tid == 0) {
        float t = 0.f;
#pragma unroll
        for (int w = 0; w < 8; w++) t += rb[w];
        g_bias[c] = 0.5f * t;
    }
}

// ---------------------------------------------------------------------------
// Kernel 2: HMMA bf16-split GEMM + argmin + fixup list; also emits g_xn.
// ---------------------------------------------------------------------------
#define STAGE 28672
#define SMEM_GEMM (2 * STAGE)
__global__ void __launch_bounds__(256, 1)
k_gemm(const float* __restrict__ X, const int* __restrict__ labels,
       float* __restrict__ out) {
    extern __shared__ char sm[];
    const uint32_t sb = smem_u32(sm);
    const int tid = threadIdx.x, wid = tid >> 5, lane = tid & 31;
    const int i0 = blockIdx.x * BMG;
    const int mwarp = wid & 3, nwarp = wid >> 2;

    const int r = tid >> 1, h = tid & 1;
    const float* xrow = X + (size_t)(i0 + r) * DIM + h * 16;
    const uint4* mb4 = (const uint4*)g_mbf;

    float d[2][6][4];
#pragma unroll
    for (int a = 0; a < 2; a++)
#pragma unroll
        for (int b = 0; b < 6; b++)
#pragma unroll
            for (int e = 0; e < 4; e++) d[a][b][e] = 0.f;

    unsigned long long xnacc = 0ull;

    float4 cur0, cur1, cur2, cur3;
#define GLOAD(t)                                                    \
    {   const float4* p4 = (const float4*)(xrow + (t) * 32);        \
        cur0 = p4[0]; cur1 = p4[1]; cur2 = p4[2]; cur3 = p4[3]; }

#define GSTORE(t, buf)                                                          \
    {   float f[16];                                                            \
        *(float4*)(f + 0) = cur0; *(float4*)(f + 4) = cur1;                     \
        *(float4*)(f + 8) = cur2; *(float4*)(f + 12) = cur3;                    \
        const unsigned long long* fq = (const unsigned long long*)f;            \
        _Pragma("unroll") for (int v = 0; v < 8; v++) FMA2(xnacc, fq[v], fq[v], xnacc); \
        unsigned hw[8], lw[8];                                                  \
        _Pragma("unroll") for (int j = 0; j < 8; j++) {                         \
            float x0 = f[2 * j], x1 = f[2 * j + 1];                             \
            __nv_bfloat16 h0 = __float2bfloat16_rn(x0);                         \
            __nv_bfloat16 h1 = __float2bfloat16_rn(x1);                         \
            __nv_bfloat16 l0 = __float2bfloat16_rn(x0 - __bfloat162float(h0));  \
            __nv_bfloat16 l1 = __float2bfloat16_rn(x1 - __bfloat162float(h1));  \
            hw[j] = pkbf(h0, h1); lw[j] = pkbf(l0, l1);                         \
        }                                                                       \
        char* Ab = sm + (buf) * STAGE;                                          \
        const int rx = r & 7;                                                   \
        *(uint4*)(Ab + r * 128 + 16 * ((2 * h + 0) ^ rx)) = make_uint4(hw[0], hw[1], hw[2], hw[3]); \
        *(uint4*)(Ab + r * 128 + 16 * ((2 * h + 1) ^ rx)) = make_uint4(hw[4], hw[5], hw[6], hw[7]); \
        *(uint4*)(Ab + r * 128 + 16 * ((4 + 2 * h) ^ rx)) = make_uint4(lw[0], lw[1], lw[2], lw[3]); \
        *(uint4*)(Ab + r * 128 + 16 * ((5 + 2 * h) ^ rx)) = make_uint4(lw[4], lw[5], lw[6], lw[7]); \
        char* Bb = Ab + 16384;                                                  \
        _Pragma("unroll") for (int q = 0; q < 3; q++) {                         \
            int g = tid + q * 256;                                              \
            int brow = g >> 3, bch = g & 7;                                     \
            *(uint4*)(Bb + brow * 128 + 16 * (bch ^ (brow & 7))) = mb4[(t) * 768 + g]; \
        }                                                                       \
    }

    GLOAD(0);
    GSTORE(0, 0);

    for (int t = 0; t < NT; t++) {
        const int buf = t & 1;
        if (t + 1 < NT) GLOAD(t + 1);
        __syncthreads();

        const uint32_t Abase = sb + buf * STAGE;
        const uint32_t Bbase = Abase + 16384;

        uint32_t afr[2][2][2][4];
#pragma unroll
        for (int mt = 0; mt < 2; mt++) {
            int rowA = mwarp * 32 + mt * 16 + (lane & 15);
            uint32_t rbase = Abase + rowA * 128;
            int rx = rowA & 7;
#pragma unroll
            for (int pl = 0; pl < 2; pl++)
#pragma unroll
                for (int s = 0; s < 2; s++) {
                    int ch = pl * 4 + s * 2 + (lane >> 4);
                    uint32_t ad = rbase + 16 * (ch ^ rx);
                    LDSM_X4(afr[mt][pl][s][0], afr[mt][pl][s][1],
                            afr[mt][pl][s][2], afr[mt][pl][s][3], ad);
                }
        }

#pragma unroll
        for (int pp = 0; pp < 3; pp++) {
            const int apl = (pp == 2) ? 1 : 0;
            const int bpl = (pp == 1) ? 1 : 0;
#pragma unroll
            for (int np = 0; np < 3; np++) {
                int rowB = nwarp * 48 + np * 16 + (lane & 15);
                uint32_t rbase = Bbase + rowB * 128;
                int rx = rowB & 7;
#pragma unroll
                for (int s = 0; s < 2; s++) {
                    int ch = bpl * 4 + s * 2 + (lane >> 4);
                    uint32_t bd = rbase + 16 * (ch ^ rx);
                    uint32_t b0, b1, b2, b3;
                    LDSM_X4(b0, b1, b2, b3, bd);
#pragma unroll
                    for (int mt = 0; mt < 2; mt++) {
                        MMA16816(d[mt][np * 2 + 0], afr[mt][apl][s], b0, b2);
                        MMA16816(d[mt][np * 2 + 1], afr[mt][apl][s], b1, b3);
                    }
                }
            }
        }
        __syncthreads();
        if (t + 1 < NT) GSTORE(t + 1, (t + 1) & 1);
    }

    // |x|^2 per instance (pair threads 2r,2r+1 via shfl)
    {
        float lo, hi; UNPACK2(lo, hi, xnacc);
        float v = lo + hi;
        v += __shfl_xor_sync(0xffffffffu, v, 1);
        if (h == 0) g_xn[i0 + r] = v;
    }
    __syncthreads();

    float* sc = (float*)sm;
#pragma unroll
    for (int mt = 0; mt < 2; mt++) {
#pragma unroll
        for (int np = 0; np < 3; np++)
#pragma unroll
            for (int hh = 0; hh < 2; hh++) {
                int row0 = mwarp * 32 + mt * 16 + (lane >> 2);
                int col0 = nwarp * 48 + np * 16 + hh * 8 + 2 * (lane & 3);
                const float* dd = d[mt][np * 2 + hh];
                if (col0 < NC) sc[row0 * 97 + col0] = g_bias[col0] - dd[0];
                if (col0 + 1 < NC) sc[row0 * 97 + col0 + 1] = g_bias[col0 + 1] - dd[1];
                if (col0 < NC) sc[(row0 + 8) * 97 + col0] = g_bias[col0] - dd[2];
                if (col0 + 1 < NC) sc[(row0 + 8) * 97 + col0 + 1] = g_bias[col0 + 1] - dd[3];
            }
    }
    __syncthreads();

    if (tid < BMG) {
        int gi = i0 + tid;
        const float* row = sc + tid * 97;
        float best = 3e38f, sec = 3e38f;
        int bc = 0;
#pragma unroll 4
        for (int cc = 0; cc < NC; cc++) {
            float v = row[cc];
            if (v < best) { sec = best; best = v; bc = cc; }
            else if (v < sec) sec = v;
        }
        out[gi] = (float)bc;
        if (sec - best < 0.02f) {
            int slot = atomicAdd(&g_nfix, 1);
            if (slot < NI) g_fix[slot] = gi;
        }
        unsigned bal = __ballot_sync(0xffffffffu, bc == labels[gi]);
        if ((tid & 31) == 0) atomicAdd(&g_count, __popc(bal));
    }
}

// ---------------------------------------------------------------------------
// Kernel 2b: exact fp32 re-check of near-tie instances. (unchanged)
// ---------------------------------------------------------------------------
__global__ void __launch_bounds__(256) k_fixup(const float* __restrict__ X,
                                               const int* __restrict__ labels,
                                               float* __restrict__ out) {
    const int tid = threadIdx.x, w = tid >> 5, lane = tid & 31;
    __shared__ float ssc[NC];
    const int nfix = g_nfix < NI ? g_nfix : NI;
    for (int idx = blockIdx.x; idx < nfix; idx += gridDim.x) {
        const int gi = g_fix[idx];
        const float4* x4 = (const float4*)(X + (size_t)gi * DIM);
        for (int c = w; c < NC; c += 8) {
            const float4* m4 = (const float4*)(g_mmean + (size_t)c * DIM);
            float s = 0.f;
#pragma unroll
            for (int k = 0; k < 16; k++) {
                float4 a = x4[k * 32 + lane];
                float4 b = m4[k * 32 + lane];
                s += a.x * b.x + a.y * b.y + a.z * b.z + a.w * b.w;
            }
#pragma unroll
            for (int o = 16; o; o >>= 1) s += __shfl_xor_sync(0xffffffffu, s, o);
            if (lane == 0) ssc[c] = g_bias[c] - s;
        }
        __syncthreads();
        if (tid == 0) {
            float best = 3e38f;
            int bc = 0;
            for (int cc = 0; cc < NC; cc++) {
                float v = ssc[cc];
                if (v < best) { best = v; bc = cc; }
            }
            int oldbc = (int)out[gi];
            if (oldbc != bc) {
                int lab = labels[gi];
                atomicAdd(&g_count, (bc == lab) - (oldbc == lab));
                out[gi] = (float)bc;
            }
        }
        __syncthreads();
    }
}

// ---------------------------------------------------------------------------
// Kernel 3: sequential per-class update, 512 threads (1 float4/thread).
// cp.async ring; f32x2 partials; warp0-only decision + slot broadcast;
// uniform switch bank write; |x|^2 pre-gathered from g_xn.
// smem layout (dynamic): ring 32K | s_p 10x4K | s_red 64B | s_xn 4K |
//                        s_list 4K | wcnt/cnt/slot
// ---------------------------------------------------------------------------
#define U_RING  0
#define U_SP    32768
#define U_SRED  (U_SP + 10 * 4096)       /* 73728 */
#define U_SXN   (U_SRED + 64)            /* 73792 */
#define U_SLIST (U_SXN + 4096)           /* 77888 */
#define U_WCNT  (U_SLIST + 4096)         /* 81984 */
#define U_CNT   (U_WCNT + 64)
#define U_SLOT  (U_CNT + 4)
#define SMEM_UPD (U_SLOT + 4 + 8)

__global__ void __launch_bounds__(512, 1)
k_update(const float* __restrict__ X, const int* __restrict__ labels,
         const float* __restrict__ mem, const int* __restrict__ mpos,
         float* __restrict__ out) {
    extern __shared__ char smu[];
    const int c = blockIdx.x, tid = threadIdx.x;
    const int w = tid >> 5, lane = tid & 31;
    if (c == 0 && tid == 0) out[NI] = (float)g_count * (1.0f / NI);

    int*   s_list = (int*)(smu + U_SLIST);
    int*   s_wcnt = (int*)(smu + U_WCNT);
    int*   s_cnt  = (int*)(smu + U_CNT);
    int*   s_slot = (int*)(smu + U_SLOT);
    float* s_red  = (float*)(smu + U_SRED);
    float* s_xn   = (float*)(smu + U_SXN);

    // ---- ordered index list for class c (16 warps x 1024-segment) ----
    const int SEG = NI / 16;
    const int base = w * SEG;
    const int4* lab4 = (const int4*)labels;
    int cnt = 0;
#pragma unroll
    for (int it = 0; it < SEG / 128; it++) {
        int4 v = lab4[(base >> 2) + it * 32 + lane];
        cnt += (v.x == c) + (v.y == c) + (v.z == c) + (v.w == c);
    }
#pragma unroll
    for (int o = 16; o; o >>= 1) cnt += __shfl_xor_sync(0xffffffffu, cnt, o);
    if (lane == 0) s_wcnt[w] = cnt;
    __syncthreads();
    if (tid == 0) {
        int t = 0;
        for (int ww = 0; ww < 16; ww++) { int v = s_wcnt[ww]; s_wcnt[ww] = t; t += v; }
        *s_cnt = t;
    }
    __syncthreads();
    int off = s_wcnt[w];
#pragma unroll
    for (int it = 0; it < SEG / 128; it++) {
        int gidx = base + it * 128 + lane * 4;
        int4 v = lab4[gidx >> 2];
        int m0 = (v.x == c), m1 = (v.y == c), m2 = (v.z == c), m3 = (v.w == c);
        int nm = m0 + m1 + m2 + m3;
        int x = nm;
#pragma unroll
        for (int o = 1; o < 32; o <<= 1) {
            int y = __shfl_up_sync(0xffffffffu, x, o);
            if (lane >= o) x += y;
        }
        int p2 = off + x - nm;
        if (m0) { s_list[p2 < 1024 ? p2 : 1023] = gidx + 0; p2++; }
        if (m1) { s_list[p2 < 1024 ? p2 : 1023] = gidx + 1; p2++; }
        if (m2) { s_list[p2 < 1024 ? p2 : 1023] = gidx + 2; p2++; }
        if (m3) { s_list[p2 < 1024 ? p2 : 1023] = gidx + 3; p2++; }
        off += __shfl_sync(0xffffffffu, x, 31);
    }
    __syncthreads();

    const int n = *s_cnt < 1024 ? *s_cnt : 1024;

    // ---- gather |x|^2 for the list ----
    for (int i = tid; i < n; i += 512) s_xn[i] = g_xn[s_list[i]];

    // ---- warm the cp.async ring (one 16B chunk per thread per row) ----
    const uint32_t ringD = smem_u32(smu) + tid * 16;
#pragma unroll
    for (int dpt = 0; dpt < 4; dpt++) {
        if (dpt < n) CPA16(ringD + dpt * 8192, X + (size_t)s_list[dpt] * DIM + tid * 4);
        CPCOMMIT();
    }

    // ---- bank into registers (1 float4/thread as ulonglong2) ----
    const ulonglong2* memU = (const ulonglong2*)mem + (size_t)c * BK * (DIM / 4);
    ulonglong2 br0, br1, br2, br3, br4, br5, br6, br7, br8, br9;
    br0 = memU[0 * 512 + tid]; br1 = memU[1 * 512 + tid];
    br2 = memU[2 * 512 + tid]; br3 = memU[3 * 512 + tid];
    br4 = memU[4 * 512 + tid]; br5 = memU[5 * 512 + tid];
    br6 = memU[6 * 512 + tid]; br7 = memU[7 * 512 + tid];
    br8 = memU[8 * 512 + tid]; br9 = memU[9 * 512 + tid];

#define DOTS(XA)                                                               \
    {                                                                          \
        unsigned long long pa;                                                 \
        pa = 0ull; FMA2(pa, br0.x, (XA).x, pa); FMA2(pa, br0.y, (XA).y, pa);   \
        *(unsigned long long*)(smu + U_SP + 0 * 4096 + tid * 8) = pa;          \
        pa = 0ull; FMA2(pa, br1.x, (XA).x, pa); FMA2(pa, br1.y, (XA).y, pa);   \
        *(unsigned long long*)(smu + U_SP + 1 * 4096 + tid * 8) = pa;          \
        pa = 0ull; FMA2(pa, br2.x, (XA).x, pa); FMA2(pa, br2.y, (XA).y, pa);   \
        *(unsigned long long*)(smu + U_SP + 2 * 4096 + tid * 8) = pa;          \
        pa = 0ull; FMA2(pa, br3.x, (XA).x, pa); FMA2(pa, br3.y, (XA).y, pa);   \
        *(unsigned long long*)(smu + U_SP + 3 * 4096 + tid * 8) = pa;          \
        pa = 0ull; FMA2(pa, br4.x, (XA).x, pa); FMA2(pa, br4.y, (XA).y, pa);   \
        *(unsigned long long*)(smu + U_SP + 4 * 4096 + tid * 8) = pa;          \
        pa = 0ull; FMA2(pa, br5.x, (XA).x, pa); FMA2(pa, br5.y, (XA).y, pa);   \
        *(unsigned long long*)(smu + U_SP + 5 * 4096 + tid * 8) = pa;          \
        pa = 0ull; FMA2(pa, br6.x, (XA).x, pa); FMA2(pa, br6.y, (XA).y, pa);   \
        *(unsigned long long*)(smu + U_SP + 6 * 4096 + tid * 8) = pa;          \
        pa = 0ull; FMA2(pa, br7.x, (XA).x, pa); FMA2(pa, br7.y, (XA).y, pa);   \
        *(unsigned long long*)(smu + U_SP + 7 * 4096 + tid * 8) = pa;          \
        pa = 0ull; FMA2(pa, br8.x, (XA).x, pa); FMA2(pa, br8.y, (XA).y, pa);   \
        *(unsigned long long*)(smu + U_SP + 8 * 4096 + tid * 8) = pa;          \
        pa = 0ull; FMA2(pa, br9.x, (XA).x, pa); FMA2(pa, br9.y, (XA).y, pa);   \
        *(unsigned long long*)(smu + U_SP + 9 * 4096 + tid * 8) = pa;          \
    }

    // stage B: warps 0..9 each reduce one 512-entry f32x2 row -> s_red[w]
#define STAGE_B()                                                              \
    if (w < BK) {                                                              \
        const char* rowp = smu + U_SP + w * 4096;                              \
        unsigned long long acc = 0ull;                                         \
        _Pragma("unroll") for (int ch = 0; ch < 8; ch++) {                     \
            ulonglong2 q = *(const ulonglong2*)(rowp + ch * 512 + lane * 16);  \
            ADD2(acc, acc, q.x); ADD2(acc, acc, q.y);                          \
        }                                                                      \
        float lo, hi; UNPACK2(lo, hi, acc);                                    \
        float v = lo + hi;                                                     \
        _Pragma("unroll") for (int o = 16; o; o >>= 1)                         \
            v += __shfl_xor_sync(0xffffffffu, v, o);                           \
        if (lane == 0) s_red[w] = v;                                           \
    }

    // prologue: bank norms -> bn (lane-sliced in warp 0)
    {
        unsigned long long pa;
        ulonglong2 bb[10] = {br0, br1, br2, br3, br4, br5, br6, br7, br8, br9};
#pragma unroll
        for (int j = 0; j < BK; j++) {
            pa = 0ull; FMA2(pa, bb[j].x, bb[j].x, pa); FMA2(pa, bb[j].y, bb[j].y, pa);
            *(unsigned long long*)(smu + U_SP + j * 4096 + tid * 8) = pa;
        }
    }
    __syncthreads();
    STAGE_B();
    __syncthreads();
    float bn_l = (w == 0 && lane < BK) ? s_red[lane] : 0.f;
    __syncthreads();

    // ---- sequential scan ----
    int p = mpos[c];
    for (int s = 0; s < n; s++) {
        CPWAIT3();
        ulonglong2 XA = *(const ulonglong2*)(smu + (s & 3) * 8192 + tid * 16);
        if (s + 4 < n) CPA16(ringD + (s & 3) * 8192, X + (size_t)s_list[s + 4] * DIM + tid * 4);
        CPCOMMIT();

        DOTS(XA);
        __syncthreads();
        STAGE_B();
        __syncthreads();

        if (w == 0) {
            float xxv = s_xn[s];
            int slot;
            if (p < BK) {
                slot = p;
            } else {
                float tot = s_red[lane < BK ? lane : 0];
                float dd = (lane < BK) ? fmaf(-2.f, tot, bn_l) : -CUDART_INF_F;
                float mx = dd;
#pragma unroll
                for (int o = 16; o; o >>= 1) mx = fmaxf(mx, __shfl_xor_sync(0xffffffffu, mx, o));
                unsigned bal = __ballot_sync(0xffffffffu, dd == mx) & 0x3FFu;
                slot = __ffs(bal) - 1;
            }
            if (lane == slot) bn_l = xxv;
            if (lane == 0) *s_slot = slot;
        }
        __syncthreads();

        switch (*s_slot) {
            case 0: br0 = XA; break;
            case 1: br1 = XA; break;
            case 2: br2 = XA; break;
            case 3: br3 = XA; break;
            case 4: br4 = XA; break;
            case 5: br5 = XA; break;
            case 6: br6 = XA; break;
            case 7: br7 = XA; break;
            case 8: br8 = XA; break;
            default: br9 = XA; break;
        }
        if (p < BK) p++;
    }

    // ---- epilogue (out+16385 only 4B-aligned -> scalar stores) ----
    float* om = out + (NI + 1) + (size_t)c * BK * DIM + tid * 4;
    {
        ulonglong2 bb[10] = {br0, br1, br2, br3, br4, br5, br6, br7, br8, br9};
#pragma unroll
        for (int j = 0; j < BK; j++) {
            float f0, f1, f2, f3;
            UNPACK2(f0, f1, bb[j].x); UNPACK2(f2, f3, bb[j].y);
            om[j * DIM + 0] = f0; om[j * DIM + 1] = f1;
            om[j * DIM + 2] = f2; om[j * DIM + 3] = f3;
        }
    }
    if (tid == 0) out[(NI + 1) + (size_t)NC * BK * DIM + c] = (float)p;
}

// ---------------------------------------------------------------------------
extern "C" void kernel_launch(void* const* d_in, const int* in_sizes, int n_in,
                              void* d_out, int out_size) {
    const float* X      = (const float*)d_in[0];
    const int*   labels = (const int*)d_in[1];
    const float* mem    = (const float*)d_in[2];
    const int*   mpos   = (const int*)d_in[3];
    float* out = (float*)d_out;

    static bool init = false;
    if (!init) {
        init = true;
        cudaFuncSetAttribute(k_gemm, cudaFuncAttributeMaxDynamicSharedMemorySize, SMEM_GEMM);
        cudaFuncSetAttribute(k_update, cudaFuncAttributeMaxDynamicSharedMemorySize, SMEM_UPD);
    }

    k_mean<<<NCP, 256>>>(mem);
    k_gemm<<<NI / BMG, 256, SMEM_GEMM>>>(X, labels, out);
    k_fixup<<<296, 256>>>(X, labels, out);
    k_update<<<NC, 512, SMEM_UPD>>>(X, labels, mem, mpos, out);
}

// round 8
// speedup vs baseline: 1.5664x; 1.5664x over previous
#include <cuda_runtime.h>
#include <cuda_bf16.h>
#include <math_constants.h>
#include <cstdint>

#define NC   81
#define NCP  96
#define BK   10
#define DIM  2048
#define NI   16384
#define NT   64          /* k-tiles of 32 fp32 dims */
#define BMG  128         /* gemm instances per block */

__device__ int   g_count;
__device__ int   g_nfix;
__device__ int   g_fix[NI];
__device__ float g_bias[NCP];
__device__ float g_mmean[NC * DIM];
// [tile][class][hi(32)|lo(32)] bf16 => 128B per class-row per tile
__device__ __align__(16) unsigned short g_mbf[NT * NCP * 64];

__device__ __forceinline__ uint32_t smem_u32(const void* p) {
    uint32_t a;
    asm("{ .reg .u64 t; cvta.to.shared.u64 t, %1; cvt.u32.u64 %0, t; }" : "=r"(a) : "l"(p));
    return a;
}

#define LDSM_X4(r0, r1, r2, r3, addr)                                         \
    asm volatile("ldmatrix.sync.aligned.m8n8.x4.shared.b16 {%0,%1,%2,%3}, [%4];" \
                 : "=r"(r0), "=r"(r1), "=r"(r2), "=r"(r3) : "r"(addr))

#define MMA16816(d, a, b0v, b1v)                                              \
    asm volatile("mma.sync.aligned.m16n8k16.row.col.f32.bf16.bf16.f32 "       \
                 "{%0,%1,%2,%3},{%4,%5,%6,%7},{%8,%9},{%0,%1,%2,%3};"         \
                 : "+f"((d)[0]), "+f"((d)[1]), "+f"((d)[2]), "+f"((d)[3])     \
                 : "r"((a)[0]), "r"((a)[1]), "r"((a)[2]), "r"((a)[3]),        \
                   "r"(b0v), "r"(b1v))

#define FMA2(d, a, b, c) asm("fma.rn.f32x2 %0, %1, %2, %3;" : "=l"(d) : "l"(a), "l"(b), "l"(c))
#define UNPACK2(lo, hi, v) asm("mov.b64 {%0, %1}, %2;" : "=f"(lo), "=f"(hi) : "l"(v))

#define CPA16(dst, src) asm volatile("cp.async.cg.shared.global [%0], [%1], 16;" :: "r"(dst), "l"(src) : "memory")
#define CPCOMMIT()      asm volatile("cp.async.commit_group;" ::: "memory")
#define CPWAIT3()       asm volatile("cp.async.wait_group 3;" ::: "memory")

__device__ __forceinline__ unsigned pkbf(__nv_bfloat16 a, __nv_bfloat16 b) {
    return ((unsigned)__bfloat16_as_ushort(b) << 16) | (unsigned)__bfloat16_as_ushort(a);
}

// ---------------------------------------------------------------------------
// Kernel 1: class means -> fp32 plane + bf16 hi/lo planes + bias; zero pads.
// ---------------------------------------------------------------------------
__global__ void k_mean(const float* __restrict__ mem) {
    int c = blockIdx.x, tid = threadIdx.x;
    if (c == 0 && tid == 0) { g_count = 0; g_nfix = 0; }
    if (c >= NC) {
        for (int d = tid; d < DIM; d += 256) {
            int tt = d >> 5, j = d & 31;
            g_mbf[(tt * NCP + c) * 64 + j] = 0;
            g_mbf[(tt * NCP + c) * 64 + 32 + j] = 0;
        }
        return;
    }
    float part = 0.f;
    for (int d = tid; d < DIM; d += 256) {
        float s = 0.f;
#pragma unroll
        for (int b = 0; b < BK; b++) s += mem[(size_t)(c * BK + b) * DIM + d];
        float m = s * (1.0f / BK);
        g_mmean[c * DIM + d] = m;
        __nv_bfloat16 hi = __float2bfloat16_rn(m);
        __nv_bfloat16 lo = __float2bfloat16_rn(m - __bfloat162float(hi));
        int tt = d >> 5, j = d & 31;
        g_mbf[(tt * NCP + c) * 64 + j] = __bfloat16_as_ushort(hi);
        g_mbf[(tt * NCP + c) * 64 + 32 + j] = __bfloat16_as_ushort(lo);
        part += m * m;
    }
#pragma unroll
    for (int o = 16; o; o >>= 1) part += __shfl_xor_sync(0xffffffffu, part, o);
    __shared__ float rb[8];
    if ((tid & 31) == 0) rb[tid >> 5] = part;
    __syncthreads();
    if (tid == 0) {
        float t = 0.f;
#pragma unroll
        for (int w = 0; w < 8; w++) t += rb[w];
        g_bias[c] = 0.5f * t;
    }
}

// ---------------------------------------------------------------------------
// GEMM path (blocks 81..208): HMMA bf16-split GEMM + argmin + fixup list.
// ---------------------------------------------------------------------------
#define STAGE 28672
#define SMEM_FUSED (2 * STAGE)   /* 57344; update path uses ~48KB of it */

__device__ __forceinline__ void gemm_path(char* sm, const float* __restrict__ X,
                                          const int* __restrict__ labels,
                                          float* __restrict__ out, int gb) {
    const uint32_t sb = smem_u32(sm);
    const int tid = threadIdx.x, wid = tid >> 5, lane = tid & 31;
    const int i0 = gb * BMG;
    const int mwarp = wid & 3, nwarp = wid >> 2;

    const int r = tid >> 1, h = tid & 1;
    const float* xrow = X + (size_t)(i0 + r) * DIM + h * 16;
    const uint4* mb4 = (const uint4*)g_mbf;

    float d[2][6][4];
#pragma unroll
    for (int a = 0; a < 2; a++)
#pragma unroll
        for (int b = 0; b < 6; b++)
#pragma unroll
            for (int e = 0; e < 4; e++) d[a][b][e] = 0.f;

    float4 cur0, cur1, cur2, cur3;
#define GLOAD(t)                                                    \
    {   const float4* p4 = (const float4*)(xrow + (t) * 32);        \
        cur0 = p4[0]; cur1 = p4[1]; cur2 = p4[2]; cur3 = p4[3]; }

#define GSTORE(t, buf)                                                          \
    {   float f[16];                                                            \
        *(float4*)(f + 0) = cur0; *(float4*)(f + 4) = cur1;                     \
        *(float4*)(f + 8) = cur2; *(float4*)(f + 12) = cur3;                    \
        unsigned hw[8], lw[8];                                                  \
        _Pragma("unroll") for (int j = 0; j < 8; j++) {                         \
            float x0 = f[2 * j], x1 = f[2 * j + 1];                             \
            __nv_bfloat16 h0 = __float2bfloat16_rn(x0);                         \
            __nv_bfloat16 h1 = __float2bfloat16_rn(x1);                         \
            __nv_bfloat16 l0 = __float2bfloat16_rn(x0 - __bfloat162float(h0));  \
            __nv_bfloat16 l1 = __float2bfloat16_rn(x1 - __bfloat162float(h1));  \
            hw[j] = pkbf(h0, h1); lw[j] = pkbf(l0, l1);                         \
        }                                                                       \
        char* Ab = sm + (buf) * STAGE;                                          \
        const int rx = r & 7;                                                   \
        *(uint4*)(Ab + r * 128 + 16 * ((2 * h + 0) ^ rx)) = make_uint4(hw[0], hw[1], hw[2], hw[3]); \
        *(uint4*)(Ab + r * 128 + 16 * ((2 * h + 1) ^ rx)) = make_uint4(hw[4], hw[5], hw[6], hw[7]); \
        *(uint4*)(Ab + r * 128 + 16 * ((4 + 2 * h) ^ rx)) = make_uint4(lw[0], lw[1], lw[2], lw[3]); \
        *(uint4*)(Ab + r * 128 + 16 * ((5 + 2 * h) ^ rx)) = make_uint4(lw[4], lw[5], lw[6], lw[7]); \
        char* Bb = Ab + 16384;                                                  \
        _Pragma("unroll") for (int q = 0; q < 3; q++) {                         \
            int g = tid + q * 256;                                              \
            int brow = g >> 3, bch = g & 7;                                     \
            *(uint4*)(Bb + brow * 128 + 16 * (bch ^ (brow & 7))) = mb4[(t) * 768 + g]; \
        }                                                                       \
    }

    GLOAD(0);
    GSTORE(0, 0);

    for (int t = 0; t < NT; t++) {
        const int buf = t & 1;
        if (t + 1 < NT) GLOAD(t + 1);
        __syncthreads();

        const uint32_t Abase = sb + buf * STAGE;
        const uint32_t Bbase = Abase + 16384;

        uint32_t afr[2][2][2][4];
#pragma unroll
        for (int mt = 0; mt < 2; mt++) {
            int rowA = mwarp * 32 + mt * 16 + (lane & 15);
            uint32_t rbase = Abase + rowA * 128;
            int rx = rowA & 7;
#pragma unroll
            for (int pl = 0; pl < 2; pl++)
#pragma unroll
                for (int s = 0; s < 2; s++) {
                    int ch = pl * 4 + s * 2 + (lane >> 4);
                    uint32_t ad = rbase + 16 * (ch ^ rx);
                    LDSM_X4(afr[mt][pl][s][0], afr[mt][pl][s][1],
                            afr[mt][pl][s][2], afr[mt][pl][s][3], ad);
                }
        }

#pragma unroll
        for (int pp = 0; pp < 3; pp++) {
            const int apl = (pp == 2) ? 1 : 0;
            const int bpl = (pp == 1) ? 1 : 0;
#pragma unroll
            for (int np = 0; np < 3; np++) {
                int rowB = nwarp * 48 + np * 16 + (lane & 15);
                uint32_t rbase = Bbase + rowB * 128;
                int rx = rowB & 7;
#pragma unroll
                for (int s = 0; s < 2; s++) {
                    int ch = bpl * 4 + s * 2 + (lane >> 4);
                    uint32_t bd = rbase + 16 * (ch ^ rx);
                    uint32_t b0, b1, b2, b3;
                    LDSM_X4(b0, b1, b2, b3, bd);
#pragma unroll
                    for (int mt = 0; mt < 2; mt++) {
                        MMA16816(d[mt][np * 2 + 0], afr[mt][apl][s], b0, b2);
                        MMA16816(d[mt][np * 2 + 1], afr[mt][apl][s], b1, b3);
                    }
                }
            }
        }
        __syncthreads();
        if (t + 1 < NT) GSTORE(t + 1, (t + 1) & 1);
    }
    __syncthreads();

    float* sc = (float*)sm;
#pragma unroll
    for (int mt = 0; mt < 2; mt++) {
#pragma unroll
        for (int np = 0; np < 3; np++)
#pragma unroll
            for (int hh = 0; hh < 2; hh++) {
                int row0 = mwarp * 32 + mt * 16 + (lane >> 2);
                int col0 = nwarp * 48 + np * 16 + hh * 8 + 2 * (lane & 3);
                const float* dd = d[mt][np * 2 + hh];
                if (col0 < NC) sc[row0 * 97 + col0] = g_bias[col0] - dd[0];
                if (col0 + 1 < NC) sc[row0 * 97 + col0 + 1] = g_bias[col0 + 1] - dd[1];
                if (col0 < NC) sc[(row0 + 8) * 97 + col0] = g_bias[col0] - dd[2];
                if (col0 + 1 < NC) sc[(row0 + 8) * 97 + col0 + 1] = g_bias[col0 + 1] - dd[3];
            }
    }
    __syncthreads();

    if (tid < BMG) {
        int gi = i0 + tid;
        const float* row = sc + tid * 97;
        float best = 3e38f, sec = 3e38f;
        int bc = 0;
#pragma unroll 4
        for (int cc = 0; cc < NC; cc++) {
            float v = row[cc];
            if (v < best) { sec = best; best = v; bc = cc; }
            else if (v < sec) sec = v;
        }
        out[gi] = (float)bc;
        if (sec - best < 0.02f) {
            int slot = atomicAdd(&g_nfix, 1);
            if (slot < NI) g_fix[slot] = gi;
        }
        unsigned bal = __ballot_sync(0xffffffffu, bc == labels[gi]);
        if ((tid & 31) == 0) atomicAdd(&g_count, __popc(bal));
    }
}

// ---------------------------------------------------------------------------
// Update path (blocks 0..80): sequential per-class update — R6 structure.
// cp.async ring + smem transpose-reduction; dynamic smem layout:
// ring 32K | s_p 11x1K | s_list 4K | s_red 64B | s_wcnt 32B | s_cnt
// ---------------------------------------------------------------------------
__device__ __forceinline__ void update_path(char* smu, const float* __restrict__ X,
                                            const int* __restrict__ labels,
                                            const float* __restrict__ mem,
                                            const int* __restrict__ mpos,
                                            float* __restrict__ out) {
    const int c = blockIdx.x, tid = threadIdx.x;
    const int w = tid >> 5, lane = tid & 31;

    float* s_x    = (float*)smu;                    // [4][DIM]
    float* s_p    = (float*)(smu + 32768);          // [11][256]
    int*   s_list = (int*)(smu + 44032);            // [1024]
    float* s_red  = (float*)(smu + 48128);          // [12], 16B aligned
    int*   s_wcnt = (int*)(smu + 48192);            // [8]
    int*   s_cnt  = (int*)(smu + 48224);

    // ---- ordered index list for class c ----
    const int SEG = NI / 8;
    const int base = w * SEG;
    const int4* lab4 = (const int4*)labels;
    int cnt = 0;
    for (int it = 0; it < SEG / 128; it++) {
        int4 v = lab4[(base >> 2) + it * 32 + lane];
        cnt += (v.x == c) + (v.y == c) + (v.z == c) + (v.w == c);
    }
#pragma unroll
    for (int o = 16; o; o >>= 1) cnt += __shfl_xor_sync(0xffffffffu, cnt, o);
    if (lane == 0) s_wcnt[w] = cnt;
    __syncthreads();
    if (tid == 0) {
        int t = 0;
        for (int ww = 0; ww < 8; ww++) { int v = s_wcnt[ww]; s_wcnt[ww] = t; t += v; }
        *s_cnt = t;
    }
    __syncthreads();
    int off = s_wcnt[w];
    for (int it = 0; it < SEG / 128; it++) {
        int gidx = base + it * 128 + lane * 4;
        int4 v = lab4[gidx >> 2];
        int m0 = (v.x == c), m1 = (v.y == c), m2 = (v.z == c), m3 = (v.w == c);
        int nm = m0 + m1 + m2 + m3;
        int x = nm;
#pragma unroll
        for (int o = 1; o < 32; o <<= 1) {
            int y = __shfl_up_sync(0xffffffffu, x, o);
            if (lane >= o) x += y;
        }
        int p2 = off + x - nm;
        if (m0) { s_list[p2 < 1024 ? p2 : 1023] = gidx + 0; p2++; }
        if (m1) { s_list[p2 < 1024 ? p2 : 1023] = gidx + 1; p2++; }
        if (m2) { s_list[p2 < 1024 ? p2 : 1023] = gidx + 2; p2++; }
        if (m3) { s_list[p2 < 1024 ? p2 : 1023] = gidx + 3; p2++; }
        off += __shfl_sync(0xffffffffu, x, 31);
    }
    __syncthreads();

    const int n = *s_cnt < 1024 ? *s_cnt : 1024;

    // ---- warm the cp.async ring with rows 0..3 (per-thread 2x16B) ----
    const uint32_t ringA = smem_u32(s_x) + tid * 16;
    const uint32_t ringB = ringA + 4096;
#pragma unroll
    for (int dpt = 0; dpt < 4; dpt++) {
        if (dpt < n) {
            const float* src = X + (size_t)s_list[dpt] * DIM + tid * 4;
            CPA16(ringA + dpt * 8192, src);
            CPA16(ringB + dpt * 8192, src + 1024);
        }
        CPCOMMIT();
    }

    // ---- bank into registers (f32x2 pairs); |b_j|^2 via smem reduction ----
    const ulonglong2* memU = (const ulonglong2*)mem + (size_t)c * BK * (DIM / 4);
    ulonglong2 br[BK][2];
#pragma unroll
    for (int j = 0; j < BK; j++) {
        br[j][0] = memU[j * 512 + tid];
        br[j][1] = memU[j * 512 + 256 + tid];
        unsigned long long pa = 0ull;
        FMA2(pa, br[j][0].x, br[j][0].x, pa);
        FMA2(pa, br[j][0].y, br[j][0].y, pa);
        FMA2(pa, br[j][1].x, br[j][1].x, pa);
        FMA2(pa, br[j][1].y, br[j][1].y, pa);
        float lo, hi; UNPACK2(lo, hi, pa);
        s_p[j * 256 + tid] = lo + hi;
    }
    s_p[10 * 256 + tid] = 0.f;
    __syncthreads();

#define STAGE_B()                                                             \
    {                                                                         \
        {                                                                     \
            const float4* rp = (const float4*)(s_p + w * 256);                \
            float4 a0 = rp[lane], a1 = rp[lane + 32];                         \
            float v = (a0.x + a0.y) + (a0.z + a0.w) +                         \
                      (a1.x + a1.y) + (a1.z + a1.w);                          \
            _Pragma("unroll") for (int o = 16; o; o >>= 1)                    \
                v += __shfl_xor_sync(0xffffffffu, v, o);                      \
            if (lane == 0) s_red[w] = v;                                      \
        }                                                                     \
        if (w < 3) {                                                          \
            const float4* rp = (const float4*)(s_p + (8 + w) * 256);          \
            float4 a0 = rp[lane], a1 = rp[lane + 32];                         \
            float v = (a0.x + a0.y) + (a0.z + a0.w) +                         \
                      (a1.x + a1.y) + (a1.z + a1.w);                          \
            _Pragma("unroll") for (int o = 16; o; o >>= 1)                    \
                v += __shfl_xor_sync(0xffffffffu, v, o);                      \
            if (lane == 0) s_red[8 + w] = v;                                  \
        }                                                                     \
    }

    STAGE_B();
    __syncthreads();

    float bn[BK];
    {
        float4 ra = *(const float4*)s_red;
        float4 rb2 = *(const float4*)(s_red + 4);
        float4 rc = *(const float4*)(s_red + 8);
        bn[0] = ra.x; bn[1] = ra.y; bn[2] = ra.z; bn[3] = ra.w;
        bn[4] = rb2.x; bn[5] = rb2.y; bn[6] = rb2.z; bn[7] = rb2.w;
        bn[8] = rc.x; bn[9] = rc.y;
    }
    __syncthreads();

    // ---- sequential scan ----
    int p = mpos[c];
    for (int s = 0; s < n; s++) {
        CPWAIT3();
        const float* xr = s_x + (s & 3) * DIM;
        float4 xa = *(const float4*)(xr + tid * 4);
        float4 xb = *(const float4*)(xr + 1024 + tid * 4);
        if (s + 4 < n) {
            const float* src = X + (size_t)s_list[s + 4] * DIM + tid * 4;
            CPA16(ringA + (s & 3) * 8192, src);
            CPA16(ringB + (s & 3) * 8192, src + 1024);
        }
        CPCOMMIT();

        ulonglong2 X0 = *(ulonglong2*)&xa;
        ulonglong2 X1 = *(ulonglong2*)&xb;
#pragma unroll
        for (int j = 0; j < BK; j++) {
            unsigned long long pa = 0ull;
            FMA2(pa, br[j][0].x, X0.x, pa);
            FMA2(pa, br[j][0].y, X0.y, pa);
            FMA2(pa, br[j][1].x, X1.x, pa);
            FMA2(pa, br[j][1].y, X1.y, pa);
            float lo, hi; UNPACK2(lo, hi, pa);
            s_p[j * 256 + tid] = lo + hi;
        }
        {
            unsigned long long pa = 0ull;
            FMA2(pa, X0.x, X0.x, pa); FMA2(pa, X0.y, X0.y, pa);
            FMA2(pa, X1.x, X1.x, pa); FMA2(pa, X1.y, X1.y, pa);
            float lo, hi; UNPACK2(lo, hi, pa);
            s_p[10 * 256 + tid] = lo + hi;
        }
        __syncthreads();

        STAGE_B();
        __syncthreads();

        float tot[11], xx;
        {
            float4 ra = *(const float4*)s_red;
            float4 rb2 = *(const float4*)(s_red + 4);
            float4 rc = *(const float4*)(s_red + 8);
            tot[0] = ra.x; tot[1] = ra.y; tot[2] = ra.z; tot[3] = ra.w;
            tot[4] = rb2.x; tot[5] = rb2.y; tot[6] = rb2.z; tot[7] = rb2.w;
            tot[8] = rc.x; tot[9] = rc.y; xx = rc.z;
        }
        int slot;
        if (p < BK) {
            slot = p;
        } else {
            float dd[BK];
#pragma unroll
            for (int j = 0; j < BK; j++) dd[j] = fmaf(-2.f, tot[j], bn[j]);
            float mx = dd[0];
#pragma unroll
            for (int j = 1; j < BK; j++) mx = fmaxf(mx, dd[j]);
            slot = BK - 1;
#pragma unroll
            for (int j = BK - 1; j >= 0; j--) slot = (dd[j] == mx) ? j : slot;
        }
#pragma unroll
        for (int j = 0; j < BK; j++) {
            bool hh = (slot == j);
            br[j][0].x = hh ? X0.x : br[j][0].x;
            br[j][0].y = hh ? X0.y : br[j][0].y;
            br[j][1].x = hh ? X1.x : br[j][1].x;
            br[j][1].y = hh ? X1.y : br[j][1].y;
            bn[j] = hh ? xx : bn[j];
        }
        if (p < BK) p++;
    }

    // ---- epilogue (out+16385 only 4B-aligned -> scalar stores) ----
    float* om = out + (NI + 1) + (size_t)c * BK * DIM;
#pragma unroll
    for (int j = 0; j < BK; j++) {
        float f0, f1, f2, f3;
        UNPACK2(f0, f1, br[j][0].x); UNPACK2(f2, f3, br[j][0].y);
        int d0 = j * DIM + tid * 4;
        om[d0 + 0] = f0; om[d0 + 1] = f1; om[d0 + 2] = f2; om[d0 + 3] = f3;
        UNPACK2(f0, f1, br[j][1].x); UNPACK2(f2, f3, br[j][1].y);
        int d1 = j * DIM + 1024 + tid * 4;
        om[d1 + 0] = f0; om[d1 + 1] = f1; om[d1 + 2] = f2; om[d1 + 3] = f3;
    }
    if (tid == 0) out[(NI + 1) + (size_t)NC * BK * DIM + c] = (float)p;
}

// ---------------------------------------------------------------------------
// Fused kernel: blocks 0..80 update, blocks 81..208 gemm — concurrent.
// ---------------------------------------------------------------------------
__global__ void __launch_bounds__(256, 1)
k_fused(const float* __restrict__ X, const int* __restrict__ labels,
        const float* __restrict__ mem, const int* __restrict__ mpos,
        float* __restrict__ out) {
    extern __shared__ char smdyn[];
    if (blockIdx.x < NC)
        update_path(smdyn, X, labels, mem, mpos, out);
    else
        gemm_path(smdyn, X, labels, out, blockIdx.x - NC);
}

// ---------------------------------------------------------------------------
// Fixup: exact fp32 re-check of near-tie instances (after gemm).
// ---------------------------------------------------------------------------
__global__ void __launch_bounds__(256) k_fixup(const float* __restrict__ X,
                                               const int* __restrict__ labels,
                                               float* __restrict__ out) {
    const int tid = threadIdx.x, w = tid >> 5, lane = tid & 31;
    __shared__ float ssc[NC];
    const int nfix = g_nfix < NI ? g_nfix : NI;
    for (int idx = blockIdx.x; idx < nfix; idx += gridDim.x) {
        const int gi = g_fix[idx];
        const float4* x4 = (const float4*)(X + (size_t)gi * DIM);
        for (int c = w; c < NC; c += 8) {
            const float4* m4 = (const float4*)(g_mmean + (size_t)c * DIM);
            float s = 0.f;
#pragma unroll
            for (int k = 0; k < 16; k++) {
                float4 a = x4[k * 32 + lane];
                float4 b = m4[k * 32 + lane];
                s += a.x * b.x + a.y * b.y + a.z * b.z + a.w * b.w;
            }
#pragma unroll
            for (int o = 16; o; o >>= 1) s += __shfl_xor_sync(0xffffffffu, s, o);
            if (lane == 0) ssc[c] = g_bias[c] - s;
        }
        __syncthreads();
        if (tid == 0) {
            float best = 3e38f;
            int bc = 0;
            for (int cc = 0; cc < NC; cc++) {
                float v = ssc[cc];
                if (v < best) { best = v; bc = cc; }
            }
            int oldbc = (int)out[gi];
            if (oldbc != bc) {
                int lab = labels[gi];
                atomicAdd(&g_count, (bc == lab) - (oldbc == lab));
                out[gi] = (float)bc;
            }
        }
        __syncthreads();
    }
}

// ---------------------------------------------------------------------------
__global__ void k_fin(float* __restrict__ out) {
    out[NI] = (float)g_count * (1.0f / NI);
}

// ---------------------------------------------------------------------------
extern "C" void kernel_launch(void* const* d_in, const int* in_sizes, int n_in,
                              void* d_out, int out_size) {
    const float* X      = (const float*)d_in[0];
    const int*   labels = (const int*)d_in[1];
    const float* mem    = (const float*)d_in[2];
    const int*   mpos   = (const int*)d_in[3];
    float* out = (float*)d_out;

    static bool init = false;
    if (!init) {
        init = true;
        cudaFuncSetAttribute(k_fused, cudaFuncAttributeMaxDynamicSharedMemorySize, SMEM_FUSED);
    }

    k_mean<<<NCP, 256>>>(mem);
    k_fused<<<NC + NI / BMG, 256, SMEM_FUSED>>>(X, labels, mem, mpos, out);
    k_fixup<<<296, 256>>>(X, labels, out);
    k_fin<<<1, 1>>>(out);
}